// round 4
// baseline (speedup 1.0000x reference)
#include <cuda_runtime.h>
#include <math.h>

#define BMAX     256
#define SIGLEN   178
#define NFR      43          // time frames  (src cols q)
#define NFQ      33          // freq bins    (src rows p)
#define NPQ      (NFQ*NFR)   // 1419
#define COUT     64
#define CONV_OUT 89
#define NB       32          // batches per chunk
#define SPAD     40          // padded row stride (floats): 160B, 16B-aligned
#define NPARTS   48          // 6 jg * 8 rs

#define PHI_N    (89*4*7*64) // 159744
#define AY_N     (89*4*7)    // 2492
#define TW_N     (33*7)      // 231

__device__ float g_spec [NPQ * BMAX];             // [p*43+q][b]
__device__ float g_phi  [PHI_N];                  // [j][qt][ky][c]
__device__ float g_ay   [AY_N];                   // [r][pt][ky]
__device__ float g_twid [33*14];                  // [k][n-1][cos,sin]
__device__ float g_theta[89 * 89 * 16 * 64];      // [r][j][tap][c]  (32.4 MB)
__device__ float g_part [BMAX * COUT * NPARTS];

// ---- shared index helpers (MUST match between precompute and main) --------
__device__ __forceinline__ int q0raw(int j) {
    float sx = (2 * j - 3 + 0.5f) * (43.0f / 178.0f) - 0.5f;
    sx = fminf(fmaxf(sx, 0.f), 42.f);
    return (int)sx;
}
__device__ __forceinline__ int q0f(int j) { int q = q0raw(j); return q > 39 ? 39 : q; }
__device__ __forceinline__ int p0f(int r) {
    float sy = (2 * r - 3 + 0.5f) * (33.0f / 178.0f) - 0.5f;
    sy = fminf(fmaxf(sy, 0.f), 32.f);
    int p = (int)sy; return p > 29 ? 29 : p;
}
__device__ __forceinline__ float bweight(int x, int q) {
    if (x < 0 || x >= 178) return 0.f;
    float sx = fminf(fmaxf((x + 0.5f) * (43.0f / 178.0f) - 0.5f, 0.f), 42.f);
    int x0 = (int)sx; float fx = sx - (float)x0; int x1 = min(x0 + 1, 42);
    float w = 0.f;
    if (q == x0) w += 1.f - fx;
    if (q == x1) w += fx;
    return w;
}

// ---- packed f32x2 helpers --------------------------------------------------
#define PACK2(d, x)  asm("mov.b64 %0, {%1, %1};" : "=l"(d) : "f"(x))
#define UNPACK2(lo, hi, d) asm("mov.b64 {%0, %1}, %2;" : "=f"(lo), "=f"(hi) : "l"(d))
#define FFMA2(d, a, b) asm("fma.rn.f32x2 %0, %1, %2, %0;" : "+l"(d) : "l"(a), "l"(b))
#define LDSV2(s0, s1, ad) asm volatile("ld.shared.v2.b64 {%0, %1}, [%2];" \
                                       : "=l"(s0), "=l"(s1) : "r"(ad))

// ---- prep: phi (conv_w channel-fold x col-resize), ay table, twiddles ------
__global__ void prep_kernel(const float* __restrict__ w) {
    int t = blockIdx.x * blockDim.x + threadIdx.x;
    if (t < PHI_N) {
        int c  = t & 63;
        int u  = t >> 6;
        int ky = u % 7;  u /= 7;
        int qt = u & 3;
        int j  = u >> 2;
        int q  = q0f(j) + qt;
        const float* wc = w + c * 147 + ky * 7;
        float a = 0.f;
#pragma unroll
        for (int kx = 0; kx < 7; kx++) {
            float ws = wc[kx] + wc[49 + kx] + wc[98 + kx];
            a += ws * bweight(2 * j - 3 + kx, q);
        }
        g_phi[((j * 4 + qt) * 7 + ky) * 64 + c] = a;
    } else if (t < PHI_N + AY_N) {
        int t2 = t - PHI_N;
        int r = t2 / 28, rem = t2 % 28, pt = rem / 7, ky = rem % 7;
        int y = 2 * r - 3 + ky;
        float wgt = 0.f;
        if (y >= 0 && y < 178) {
            float sy = fminf(fmaxf((y + 0.5f) * (33.0f / 178.0f) - 0.5f, 0.f), 32.f);
            int y0 = (int)sy; float fy = sy - (float)y0; int y1 = min(y0 + 1, 32);
            int p = p0f(r) + pt;
            if (p == y0) wgt += 1.f - fy;
            if (p == y1) wgt += fy;
        }
        g_ay[t2] = wgt;
    } else if (t < PHI_N + AY_N + TW_N) {
        int t3 = t - PHI_N - AY_N;
        int k = t3 / 7, n = 1 + t3 % 7;
        float sn, cs;
        sincospif((float)(k * n) * (1.0f / 32.0f), &sn, &cs);
        g_twid[k * 14 + (n - 1) * 2]     = cs;
        g_twid[k * 14 + (n - 1) * 2 + 1] = sn;
    }
}

// ---- spectrogram: block = one (freq,frame), thread = batch -----------------
__global__ void spec_kernel(const float* __restrict__ x, int B) {
    int pq = blockIdx.x;            // p*43 + q
    int b  = threadIdx.x;
    if (b >= B) return;
    int k  = pq / NFR;              // freq bin
    int fr = pq % NFR;              // frame

    const float* s = x + b * SIGLEN + fr * 4;
    float v[8];
    float mean = 0.f;
#pragma unroll
    for (int n = 0; n < 8; n++) { v[n] = s[n]; mean += v[n]; }
    mean *= 0.125f;

    const float* tw = g_twid + k * 14;
    float re = 0.f, im = 0.f;
#pragma unroll
    for (int n = 1; n < 8; n++) {
        float f = v[n] - mean;
        re = fmaf(f, tw[(n - 1) * 2], re);
        im = fmaf(f, -tw[(n - 1) * 2 + 1], im);
    }
    const float SCALE = sqrtf(1.0f / (178.0f * 7.0f));
    g_spec[pq * BMAX + b] = sqrtf(re * re + im * im) * SCALE;
}

// ---- theta: Theta[r][j][pt*4+qt][c] = sum_ky ay[r,pt,ky] * Phi[j,qt,ky,c] --
// r-tiled x4 so the 7 Phi loads are reused.
__global__ void theta_kernel() {
    int j  = blockIdx.x;
    int r0 = blockIdx.y * 4;
    int tid = threadIdx.x;
    int c = tid & 63, qt = tid >> 6;

    float f[7];
#pragma unroll
    for (int ky = 0; ky < 7; ky++)
        f[ky] = g_phi[((j * 4 + qt) * 7 + ky) * 64 + c];

#pragma unroll
    for (int rr = 0; rr < 4; rr++) {
        int r = r0 + rr;
        if (r >= CONV_OUT) break;
        const float* ay = g_ay + r * 28;
#pragma unroll
        for (int pt = 0; pt < 4; pt++) {
            float th = 0.f;
#pragma unroll
            for (int ky = 0; ky < 7; ky++)
                th = fmaf(ay[pt * 7 + ky], f[ky], th);
            g_theta[((r * 89 + j) * 16 + pt * 4 + qt) * 64 + c] = th;
        }
    }
}

// ---- main: 16-tap sparse op, batched x32, FFMA2, fused relu+GAP ------------
__global__ void __launch_bounds__(256)
tap_kernel(const float* __restrict__ bias, int B) {
    extern __shared__ float s[];          // [1419][SPAD] = 227,040 B
    int tid = threadIdx.x;
    int b0  = blockIdx.z * NB;

    // coalesced LDG (g_spec is [pq][b]) + conflict-free STS
    for (int i = tid; i < NPQ * NB; i += 256) {
        int pq = i >> 5, nb = i & 31;
        int b  = b0 + nb;
        s[pq * SPAD + nb] = (b < B) ? g_spec[pq * BMAX + b] : 0.f;
    }
    __syncthreads();

    unsigned sbase;
    asm("{ .reg .u64 t; cvta.to.shared.u64 t, %1; cvt.u32.u64 %0, t; }"
        : "=r"(sbase) : "l"(s));

    int c = tid & 63, jql = tid >> 6;
    int jbase = (blockIdx.x * 4 + jql) * 4;
    int q0b = min(q0raw(jbase), 37);

    int  qoff[4], jmin[4];
    bool jv[4];
#pragma unroll
    for (int jj = 0; jj < 4; jj++) {
        int j = jbase + jj;
        jv[jj]   = (j < CONV_OUT);
        jmin[jj] = jv[jj] ? j : 88;
        qoff[jj] = q0f(jmin[jj]) - q0b;
    }

    float bc = bias[c];
    unsigned long long bc2; PACK2(bc2, bc);

    float acc[NB];
#pragma unroll
    for (int i = 0; i < NB; i++) acc[i] = 0.f;

    int rlo = (CONV_OUT * (int)blockIdx.y) / 8;
    int rhi = (CONV_OUT * ((int)blockIdx.y + 1)) / 8;

    for (int r = rlo; r < rhi; ++r) {
        int p0 = p0f(r);
        const float* trow = g_theta + (size_t)r * (89 * 1024);
        unsigned srow0 = sbase + (unsigned)((p0 * NFR + q0b) * SPAD) * 4u;

#pragma unroll
        for (int jj = 0; jj < 4; jj++) {
            const float* th = trow + jmin[jj] * 1024 + c;
            unsigned sa = srow0 + (unsigned)(qoff[jj] * SPAD) * 4u;

            float thv[16];
#pragma unroll
            for (int t = 0; t < 16; t++) thv[t] = th[t * 64];

            unsigned long long d[16];
#pragma unroll
            for (int i = 0; i < 16; i++) d[i] = bc2;

#pragma unroll
            for (int pt = 0; pt < 4; pt++) {
                unsigned a0 = sa + (unsigned)(pt * (NFR * SPAD)) * 4u;
#pragma unroll
                for (int qt = 0; qt < 4; qt++) {
                    unsigned long long T; PACK2(T, thv[pt * 4 + qt]);
                    unsigned ad = a0 + (unsigned)(qt * SPAD) * 4u;
#pragma unroll
                    for (int h = 0; h < 8; h++) {
                        unsigned long long x0, x1;
                        LDSV2(x0, x1, ad + (unsigned)(h * 16));
                        FFMA2(d[2 * h],     T, x0);
                        FFMA2(d[2 * h + 1], T, x1);
                    }
                }
            }
            if (jv[jj]) {
#pragma unroll
                for (int i = 0; i < 16; i++) {
                    float lo, hi; UNPACK2(lo, hi, d[i]);
                    acc[2 * i]     += fmaxf(lo, 0.f);
                    acc[2 * i + 1] += fmaxf(hi, 0.f);
                }
            }
        }
    }

    // block reduce over the 4 jql groups (transposed, conflict-free)
    __syncthreads();
#pragma unroll
    for (int i = 0; i < NB; i++) s[i * 256 + tid] = acc[i];
    __syncthreads();

    int part = blockIdx.y * 6 + blockIdx.x;
    for (int idx = tid; idx < 64 * NB; idx += 256) {
        int c2 = idx & 63, nb = idx >> 6;
        float v = s[nb * 256 + c2]       + s[nb * 256 + 64 + c2]
                + s[nb * 256 + 128 + c2] + s[nb * 256 + 192 + c2];
        int b = b0 + nb;
        if (b < B) g_part[(b * COUT + c2) * NPARTS + part] = v;
    }
}

// ---- final: GAP mean + FC --------------------------------------------------
__global__ void fc_kernel(const float* __restrict__ fw,
                          const float* __restrict__ fb,
                          float* __restrict__ out, int B) {
    __shared__ float sm[COUT];
    int b = blockIdx.x;
    int tid = threadIdx.x;
    float sum = 0.f;
    const float* p = g_part + (b * COUT + tid) * NPARTS;
#pragma unroll
    for (int k = 0; k < NPARTS; k++) sum += p[k];
    sm[tid] = sum;
    __syncthreads();
    if (tid < 5) {
        const float inv = 1.0f / (float)(CONV_OUT * CONV_OUT);
        float accv = fb[tid];
#pragma unroll 8
        for (int c2 = 0; c2 < COUT; c2++)
            accv = fmaf(sm[c2] * inv, fw[tid * 64 + c2], accv);
        out[b * 5 + tid] = accv;
    }
}

// ---------------------------------------------------------------------------
extern "C" void kernel_launch(void* const* d_in, const int* in_sizes, int n_in,
                              void* d_out, int out_size) {
    const float* x      = (const float*)d_in[0];
    const float* conv_w = (const float*)d_in[1];
    const float* conv_b = (const float*)d_in[2];
    const float* fc_w   = (const float*)d_in[3];
    const float* fc_b   = (const float*)d_in[4];
    float*       out    = (float*)d_out;

    int B = in_sizes[0] / SIGLEN;
    if (B > BMAX) B = BMAX;

    cudaFuncSetAttribute(tap_kernel,
                         cudaFuncAttributeMaxDynamicSharedMemorySize,
                         NPQ * SPAD * 4);

    int prep_total = PHI_N + AY_N + TW_N;
    prep_kernel<<<(prep_total + 255) / 256, 256>>>(conv_w);

    spec_kernel<<<NPQ, 256>>>(x, B);

    dim3 tgrid(89, 23);
    theta_kernel<<<tgrid, 256>>>();

    int chunks = (B + NB - 1) / NB;
    dim3 mgrid(6, 8, chunks);
    tap_kernel<<<mgrid, 256, NPQ * SPAD * 4>>>(conv_b, B);

    fc_kernel<<<B, COUT>>>(fc_w, fc_b, out, B);
}

// round 5
// speedup vs baseline: 1.1145x; 1.1145x over previous
#include <cuda_runtime.h>
#include <math.h>

#define BMAX     256
#define SIGLEN   178
#define NFR      43          // time frames  (src cols q)
#define NFQ      33          // freq bins    (src rows p)
#define NPQ      (NFQ*NFR)   // 1419
#define COUT     64
#define CONV_OUT 89
#define NB       32          // batches per block
#define RG       12          // r groups
#define JG       6           // j groups (16 j each)
#define NPARTS   (RG*JG*4)   // 288
#define PW       8           // window p rows
#define QW       12          // window q cols

#define PHI_N    (89*4*7*64)
#define AY_N     (89*4*7)
#define TW_N     (33*7)

__device__ float g_spec [NPQ * BMAX];             // [p*43+q][b]
__device__ float g_phi  [PHI_N];                  // [j][qt][ky][c]
__device__ float g_ay   [AY_N];                   // [r][pt][ky]
__device__ float g_twid [33*14];                  // [k][n-1][cos,sin]
__device__ float g_theta[89 * 89 * 64 * 16];      // [r][j][c][tap]  (32.4 MB)
__device__ float g_part [(size_t)NPARTS * BMAX * COUT];  // [part][b][c] 18.9MB

// ---- shared index helpers (MUST match between precompute and main) --------
__device__ __forceinline__ int q0raw(int j) {
    float sx = (2 * j - 3 + 0.5f) * (43.0f / 178.0f) - 0.5f;
    sx = fminf(fmaxf(sx, 0.f), 42.f);
    return (int)sx;
}
__device__ __forceinline__ int q0f(int j) { int q = q0raw(j); return q > 39 ? 39 : q; }
__device__ __forceinline__ int p0f(int r) {
    float sy = (2 * r - 3 + 0.5f) * (33.0f / 178.0f) - 0.5f;
    sy = fminf(fmaxf(sy, 0.f), 32.f);
    int p = (int)sy; return p > 29 ? 29 : p;
}
__device__ __forceinline__ float bweight(int x, int q) {
    if (x < 0 || x >= 178) return 0.f;
    float sx = fminf(fmaxf((x + 0.5f) * (43.0f / 178.0f) - 0.5f, 0.f), 42.f);
    int x0 = (int)sx; float fx = sx - (float)x0; int x1 = min(x0 + 1, 42);
    float w = 0.f;
    if (q == x0) w += 1.f - fx;
    if (q == x1) w += fx;
    return w;
}

// ---- packed f32x2 helpers --------------------------------------------------
#define PACK2(d, x)  asm("mov.b64 %0, {%1, %1};" : "=l"(d) : "f"(x))
#define UNPACK2(lo, hi, d) asm("mov.b64 {%0, %1}, %2;" : "=f"(lo), "=f"(hi) : "l"(d))
#define FFMA2(d, a, b) asm("fma.rn.f32x2 %0, %1, %2, %0;" : "+l"(d) : "l"(a), "l"(b))
#define LDSV2(s0, s1, ad) asm volatile("ld.shared.v2.b64 {%0, %1}, [%2];" \
                                       : "=l"(s0), "=l"(s1) : "r"(ad))

// ---- prep: phi (conv_w channel-fold x col-resize), ay table, twiddles ------
__global__ void prep_kernel(const float* __restrict__ w) {
    int t = blockIdx.x * blockDim.x + threadIdx.x;
    if (t < PHI_N) {
        int c  = t & 63;
        int u  = t >> 6;
        int ky = u % 7;  u /= 7;
        int qt = u & 3;
        int j  = u >> 2;
        int q  = q0f(j) + qt;
        const float* wc = w + c * 147 + ky * 7;
        float a = 0.f;
#pragma unroll
        for (int kx = 0; kx < 7; kx++) {
            float ws = wc[kx] + wc[49 + kx] + wc[98 + kx];
            a += ws * bweight(2 * j - 3 + kx, q);
        }
        g_phi[((j * 4 + qt) * 7 + ky) * 64 + c] = a;
    } else if (t < PHI_N + AY_N) {
        int t2 = t - PHI_N;
        int r = t2 / 28, rem = t2 % 28, pt = rem / 7, ky = rem % 7;
        int y = 2 * r - 3 + ky;
        float wgt = 0.f;
        if (y >= 0 && y < 178) {
            float sy = fminf(fmaxf((y + 0.5f) * (33.0f / 178.0f) - 0.5f, 0.f), 32.f);
            int y0 = (int)sy; float fy = sy - (float)y0; int y1 = min(y0 + 1, 32);
            int p = p0f(r) + pt;
            if (p == y0) wgt += 1.f - fy;
            if (p == y1) wgt += fy;
        }
        g_ay[t2] = wgt;
    } else if (t < PHI_N + AY_N + TW_N) {
        int t3 = t - PHI_N - AY_N;
        int k = t3 / 7, n = 1 + t3 % 7;
        float sn, cs;
        sincospif((float)(k * n) * (1.0f / 32.0f), &sn, &cs);
        g_twid[k * 14 + (n - 1) * 2]     = cs;
        g_twid[k * 14 + (n - 1) * 2 + 1] = sn;
    }
}

// ---- spectrogram: block = one (freq,frame), thread = batch -----------------
__global__ void spec_kernel(const float* __restrict__ x, int B) {
    int pq = blockIdx.x;            // p*43 + q
    int b  = threadIdx.x;
    if (b >= B) return;
    int k  = pq / NFR;
    int fr = pq % NFR;

    const float* s = x + b * SIGLEN + fr * 4;
    float v[8];
    float mean = 0.f;
#pragma unroll
    for (int n = 0; n < 8; n++) { v[n] = s[n]; mean += v[n]; }
    mean *= 0.125f;

    const float* tw = g_twid + k * 14;
    float re = 0.f, im = 0.f;
#pragma unroll
    for (int n = 1; n < 8; n++) {
        float f = v[n] - mean;
        re = fmaf(f, tw[(n - 1) * 2], re);
        im = fmaf(f, -tw[(n - 1) * 2 + 1], im);
    }
    const float SCALE = sqrtf(1.0f / (178.0f * 7.0f));
    g_spec[pq * BMAX + b] = sqrtf(re * re + im * im) * SCALE;
}

// ---- theta: Theta[r][j][c][tap] = sum_ky ay[r,pt,ky] * Phi[j,qt,ky,c] ------
// smem transpose so output stores are coalesced float4.
__global__ void theta_kernel() {
    __shared__ float s2[16 * 64];   // [tap][c]
    int j  = blockIdx.x;
    int r0 = blockIdx.y * 4;
    int tid = threadIdx.x;
    int c = tid & 63, qt = tid >> 6;

    float f[7];
#pragma unroll
    for (int ky = 0; ky < 7; ky++)
        f[ky] = g_phi[((j * 4 + qt) * 7 + ky) * 64 + c];

    for (int rr = 0; rr < 4; rr++) {
        int r = r0 + rr;
        if (r >= CONV_OUT) break;
        const float* ay = g_ay + r * 28;
        float th[4];
#pragma unroll
        for (int pt = 0; pt < 4; pt++) {
            float a = 0.f;
#pragma unroll
            for (int ky = 0; ky < 7; ky++)
                a = fmaf(ay[pt * 7 + ky], f[ky], a);
            th[pt] = a;
        }
        __syncthreads();
#pragma unroll
        for (int pt = 0; pt < 4; pt++)
            s2[(pt * 4 + qt) * 64 + c] = th[pt];
        __syncthreads();

        // out flat [c2][tap]: float4 t covers c2=t/4, taps 4*(t&3)+k
        float4* dst = (float4*)(g_theta + (size_t)(r * 89 + j) * 1024);
        int c2 = tid >> 2, tb = (tid & 3) * 4;
        float4 v;
        v.x = s2[(tb + 0) * 64 + c2];
        v.y = s2[(tb + 1) * 64 + c2];
        v.z = s2[(tb + 2) * 64 + c2];
        v.w = s2[(tb + 3) * 64 + c2];
        dst[tid] = v;
    }
}

// ---- main: windowed 16-tap op, 512 thr = 64c x 4jql x 2bh, FFMA2 -----------
__global__ void __launch_bounds__(512, 2)
tap_kernel(const float* __restrict__ bias, int B) {
    __shared__ float s[PW * QW * NB];   // 12 KB window [wp][wq][32b]
    int tid = threadIdx.x;
    int c   = tid & 63;
    int jql = (tid >> 6) & 3;
    int bh  = tid >> 8;

    int jg = blockIdx.x, rg = blockIdx.y;
    int b0 = blockIdx.z * NB;
    int rlo = (CONV_OUT * rg) / RG, rhi = (CONV_OUT * (rg + 1)) / RG;
    int p_base = p0f(rlo);
    int jgrp   = jg * 16;
    int q_base = q0f(jgrp);

    // stage spec window: coalesced over batch
    for (int i = tid; i < PW * QW * NB; i += 512) {
        int nb = i & 31;
        int w  = i >> 5;
        int wq = w % QW, wp = w / QW;
        int p = p_base + wp, q = q_base + wq;
        int b = b0 + nb;
        float v = 0.f;
        if (p <= 32 && q <= 42 && b < B)
            v = g_spec[(p * NFR + q) * BMAX + b];
        s[i] = v;
    }
    __syncthreads();

    unsigned sbase;
    asm("{ .reg .u64 t; cvta.to.shared.u64 t, %1; cvt.u32.u64 %0, t; }"
        : "=r"(sbase) : "l"(s));
    sbase += (unsigned)(bh * 64);   // 16-float batch-half offset

    int jbase = jgrp + jql * 4;
    int  qoffB[4], jmn[4];
    bool jv[4];
#pragma unroll
    for (int jj = 0; jj < 4; jj++) {
        int j = jbase + jj;
        jv[jj]  = (j < CONV_OUT);
        jmn[jj] = jv[jj] ? j : 88;
        qoffB[jj] = (q0f(jmn[jj]) - q_base) * 128;   // bytes: *32 floats*4
    }

    float bc = bias[c];
    unsigned long long bc2; PACK2(bc2, bc);

    float acc[16];
#pragma unroll
    for (int i = 0; i < 16; i++) acc[i] = 0.f;

    for (int r = rlo; r < rhi; ++r) {
        int wp0 = p0f(r) - p_base;
        unsigned srow = sbase + (unsigned)(wp0 * (QW * NB * 4));  // wp0*1536
        const float4* trow = (const float4*)(g_theta + (size_t)(r * 89) * 1024);

#pragma unroll
        for (int jj = 0; jj < 4; jj++) {
            const float4* tv = trow + jmn[jj] * 256 + c * 4;   // [c][tap] as 4 float4
            unsigned sa = srow + (unsigned)qoffB[jj];

            unsigned long long d[8];
#pragma unroll
            for (int i = 0; i < 8; i++) d[i] = bc2;

#pragma unroll
            for (int pt = 0; pt < 4; pt++) {
                float4 tq = tv[pt];
                unsigned long long T0, T1, T2, T3;
                PACK2(T0, tq.x); PACK2(T1, tq.y);
                PACK2(T2, tq.z); PACK2(T3, tq.w);
                unsigned a0 = sa + (unsigned)(pt * (QW * NB * 4));
#pragma unroll
                for (int qt = 0; qt < 4; qt++) {
                    unsigned long long T = (qt == 0) ? T0 : (qt == 1) ? T1
                                          : (qt == 2) ? T2 : T3;
                    unsigned ad = a0 + (unsigned)(qt * 128);
#pragma unroll
                    for (int h = 0; h < 4; h++) {
                        unsigned long long x0, x1;
                        LDSV2(x0, x1, ad + (unsigned)(h * 16));
                        FFMA2(d[2 * h],     T, x0);
                        FFMA2(d[2 * h + 1], T, x1);
                    }
                }
            }
            if (jv[jj]) {
#pragma unroll
                for (int i = 0; i < 8; i++) {
                    float lo, hi; UNPACK2(lo, hi, d[i]);
                    acc[2 * i]     += fmaxf(lo, 0.f);
                    acc[2 * i + 1] += fmaxf(hi, 0.f);
                }
            }
        }
    }

    // direct partial store: [part][b][c], coalesced over c
    int part = (rg * JG + jg) * 4 + jql;
    float* pp = g_part + (size_t)part * (BMAX * COUT);
#pragma unroll
    for (int k = 0; k < 16; k++) {
        int b = b0 + bh * 16 + k;
        if (b < B) pp[b * COUT + c] = acc[k];
    }
}

// ---- final: sum partials + GAP mean + FC -----------------------------------
__global__ void fc_kernel(const float* __restrict__ fw,
                          const float* __restrict__ fb,
                          float* __restrict__ out, int B) {
    __shared__ float sm[4][COUT];
    int b = blockIdx.x;
    int tid = threadIdx.x;
    int c = tid & 63, pg = tid >> 6;
    float sum = 0.f;
    for (int p = pg; p < NPARTS; p += 4)
        sum += g_part[(size_t)p * (BMAX * COUT) + b * COUT + c];
    sm[pg][c] = sum;
    __syncthreads();
    if (tid < COUT)
        sm[0][tid] += sm[1][tid] + sm[2][tid] + sm[3][tid];
    __syncthreads();
    if (tid < 5) {
        const float inv = 1.0f / (float)(CONV_OUT * CONV_OUT);
        float accv = fb[tid];
#pragma unroll 8
        for (int c2 = 0; c2 < COUT; c2++)
            accv = fmaf(sm[0][c2] * inv, fw[tid * 64 + c2], accv);
        out[b * 5 + tid] = accv;
    }
}

// ---------------------------------------------------------------------------
extern "C" void kernel_launch(void* const* d_in, const int* in_sizes, int n_in,
                              void* d_out, int out_size) {
    const float* x      = (const float*)d_in[0];
    const float* conv_w = (const float*)d_in[1];
    const float* conv_b = (const float*)d_in[2];
    const float* fc_w   = (const float*)d_in[3];
    const float* fc_b   = (const float*)d_in[4];
    float*       out    = (float*)d_out;

    int B = in_sizes[0] / SIGLEN;
    if (B > BMAX) B = BMAX;

    int prep_total = PHI_N + AY_N + TW_N;
    prep_kernel<<<(prep_total + 255) / 256, 256>>>(conv_w);

    spec_kernel<<<NPQ, 256>>>(x, B);

    dim3 tgrid(89, 23);
    theta_kernel<<<tgrid, 256>>>();

    int chunks = (B + NB - 1) / NB;
    dim3 mgrid(JG, RG, chunks);
    tap_kernel<<<mgrid, 512>>>(conv_b, B);

    fc_kernel<<<B, 256>>>(fc_w, fc_b, out, B);
}

// round 6
// speedup vs baseline: 1.3252x; 1.1890x over previous
#include <cuda_runtime.h>
#include <math.h>

#define BMAX     256
#define SIGLEN   178
#define NFR      43          // src cols q
#define NFQ      33          // src rows p
#define NPQ      (NFQ*NFR)   // 1419
#define COUT     64
#define CONV_OUT 89
#define NB       32          // batches per block (8 per thread)
#define RG       12          // r groups
#define JT       23          // j tiles of 4
#define NPARTS   (RG*JT)     // 276

#define PHI_N    (89*4*7*64)
#define AY_N     (89*4*7)
#define TW_N     (33*7)

__device__ __align__(16) float g_spec [NPQ * BMAX];      // [p*43+q][b]
__device__ __align__(16) float g_phi  [PHI_N];           // [j][qt][ky][c]
__device__ __align__(16) float g_ay   [AY_N];            // [r][pt][ky]
__device__ __align__(16) float g_twid [33*14];
// padded theta: [r][j][6 quads][64 c][4] = 24 taps (pt*6+qt6), 48.7 MB
__device__ __align__(16) float g_th6  [(size_t)89*89*1536];
__device__ __align__(16) float g_part [(size_t)NPARTS * BMAX * COUT];

// ---- shared index helpers --------------------------------------------------
__device__ __forceinline__ int q0raw(int j) {
    float sx = (2 * j - 3 + 0.5f) * (43.0f / 178.0f) - 0.5f;
    sx = fminf(fmaxf(sx, 0.f), 42.f);
    return (int)sx;
}
__device__ __forceinline__ int q0f(int j) { int q = q0raw(j); return q > 39 ? 39 : q; }
__device__ __forceinline__ int qbase(int jbase) { int q = q0f(jbase); return q > 37 ? 37 : q; }
__device__ __forceinline__ int p0f(int r) {
    float sy = (2 * r - 3 + 0.5f) * (33.0f / 178.0f) - 0.5f;
    sy = fminf(fmaxf(sy, 0.f), 32.f);
    int p = (int)sy; return p > 29 ? 29 : p;
}
__device__ __forceinline__ float bweight(int x, int q) {
    if (x < 0 || x >= 178) return 0.f;
    float sx = fminf(fmaxf((x + 0.5f) * (43.0f / 178.0f) - 0.5f, 0.f), 42.f);
    int x0 = (int)sx; float fx = sx - (float)x0; int x1 = min(x0 + 1, 42);
    float w = 0.f;
    if (q == x0) w += 1.f - fx;
    if (q == x1) w += fx;
    return w;
}

#define PACK2(d, x)  asm("mov.b64 %0, {%1, %1};" : "=l"(d) : "f"(x))
#define UNPACK2(lo, hi, d) asm("mov.b64 {%0, %1}, %2;" : "=f"(lo), "=f"(hi) : "l"(d))
#define FFMA2(d, a, b) asm("fma.rn.f32x2 %0, %1, %2, %0;" : "+l"(d) : "l"(a), "l"(b))

// ---- prep ------------------------------------------------------------------
__global__ void prep_kernel(const float* __restrict__ w) {
    int t = blockIdx.x * blockDim.x + threadIdx.x;
    if (t < PHI_N) {
        int c  = t & 63;
        int u  = t >> 6;
        int ky = u % 7;  u /= 7;
        int qt = u & 3;
        int j  = u >> 2;
        int q  = q0f(j) + qt;
        const float* wc = w + c * 147 + ky * 7;
        float a = 0.f;
#pragma unroll
        for (int kx = 0; kx < 7; kx++) {
            float ws = wc[kx] + wc[49 + kx] + wc[98 + kx];
            a += ws * bweight(2 * j - 3 + kx, q);
        }
        g_phi[((j * 4 + qt) * 7 + ky) * 64 + c] = a;
    } else if (t < PHI_N + AY_N) {
        int t2 = t - PHI_N;
        int r = t2 / 28, rem = t2 % 28, pt = rem / 7, ky = rem % 7;
        int y = 2 * r - 3 + ky;
        float wgt = 0.f;
        if (y >= 0 && y < 178) {
            float sy = fminf(fmaxf((y + 0.5f) * (33.0f / 178.0f) - 0.5f, 0.f), 32.f);
            int y0 = (int)sy; float fy = sy - (float)y0; int y1 = min(y0 + 1, 32);
            int p = p0f(r) + pt;
            if (p == y0) wgt += 1.f - fy;
            if (p == y1) wgt += fy;
        }
        g_ay[t2] = wgt;
    } else if (t < PHI_N + AY_N + TW_N) {
        int t3 = t - PHI_N - AY_N;
        int k = t3 / 7, n = 1 + t3 % 7;
        float sn, cs;
        sincospif((float)(k * n) * (1.0f / 32.0f), &sn, &cs);
        g_twid[k * 14 + (n - 1) * 2]     = cs;
        g_twid[k * 14 + (n - 1) * 2 + 1] = sn;
    }
}

// ---- spectrogram -----------------------------------------------------------
__global__ void spec_kernel(const float* __restrict__ x, int B) {
    int pq = blockIdx.x;
    int b  = threadIdx.x;
    if (b >= B) return;
    int k  = pq / NFR;
    int fr = pq % NFR;

    const float* s = x + b * SIGLEN + fr * 4;
    float v[8];
    float mean = 0.f;
#pragma unroll
    for (int n = 0; n < 8; n++) { v[n] = s[n]; mean += v[n]; }
    mean *= 0.125f;

    const float* tw = g_twid + k * 14;
    float re = 0.f, im = 0.f;
#pragma unroll
    for (int n = 1; n < 8; n++) {
        float f = v[n] - mean;
        re = fmaf(f, tw[(n - 1) * 2], re);
        im = fmaf(f, -tw[(n - 1) * 2 + 1], im);
    }
    const float SCALE = sqrtf(1.0f / (178.0f * 7.0f));
    g_spec[pq * BMAX + b] = sqrtf(re * re + im * im) * SCALE;
}

// ---- theta6: padded, offset baked in. [r][j][quad][c][4] -------------------
__global__ void theta6_kernel() {
    __shared__ float s6[1536];          // [quad][c][4] = 24x64
    int j  = blockIdx.x;
    int r0 = blockIdx.y * 4;
    int tid = threadIdx.x;
    int c = tid & 63, qt = tid >> 6;

    int off = q0f(j) - qbase((j >> 2) << 2);   // 0..2

    float f[7];
#pragma unroll
    for (int ky = 0; ky < 7; ky++)
        f[ky] = g_phi[((j * 4 + qt) * 7 + ky) * 64 + c];

    for (int rr = 0; rr < 4; rr++) {
        int r = r0 + rr;
        if (r >= CONV_OUT) break;
        const float* ay = g_ay + r * 28;
        float th[4];
#pragma unroll
        for (int pt = 0; pt < 4; pt++) {
            float a = 0.f;
#pragma unroll
            for (int ky = 0; ky < 7; ky++)
                a = fmaf(ay[pt * 7 + ky], f[ky], a);
            th[pt] = a;
        }
        __syncthreads();
        for (int i = tid; i < 1536; i += 256) s6[i] = 0.f;
        __syncthreads();
#pragma unroll
        for (int pt = 0; pt < 4; pt++) {
            int t = pt * 6 + qt + off;                 // tap slot
            s6[(t >> 2) * 256 + c * 4 + (t & 3)] = th[pt];
        }
        __syncthreads();
        float4* dst = (float4*)(g_th6 + (size_t)(r * 89 + j) * 1536);
        const float4* src = (const float4*)s6;
        for (int i = tid; i < 384; i += 256) dst[i] = src[i];
    }
}

// tap body: quadA pos a0..(a0+n-1) -> sv[base..], then quadB
#define FQ(T4comp, svq)  do { unsigned long long Tp; PACK2(Tp, T4comp); \
    FFMA2(d[jj][0], Tp, sv[svq][0]); FFMA2(d[jj][1], Tp, sv[svq][1]); \
    FFMA2(d[jj][2], Tp, sv[svq][2]); FFMA2(d[jj][3], Tp, sv[svq][3]); } while (0)

// ---- main tap kernel: 256 thr = 64c x 4bg(8 batches) -----------------------
__global__ void __launch_bounds__(256, 2)
tap_kernel(const float* __restrict__ bias, int B) {
    int tid = threadIdx.x;
    int c   = tid & 63;
    int bg  = tid >> 6;

    int jgt = blockIdx.x;               // 0..22
    int rg  = blockIdx.y;               // 0..11
    int b0  = blockIdx.z * NB + bg * 8;

    int jbase = jgt * 4;
    int qb    = qbase(jbase);

    int  jmn[4]; bool jv[4];
#pragma unroll
    for (int jj = 0; jj < 4; jj++) {
        int j = jbase + jj;
        jv[jj]  = (j < CONV_OUT);
        jmn[jj] = jv[jj] ? j : 88;
    }

    float bc = bias[c];
    unsigned long long bc2; PACK2(bc2, bc);

    float acc[8];
#pragma unroll
    for (int i = 0; i < 8; i++) acc[i] = 0.f;

    int rlo = (CONV_OUT * rg) / RG, rhi = (CONV_OUT * (rg + 1)) / RG;

    for (int r = rlo; r < rhi; ++r) {
        int p0 = p0f(r);
        const float4* tb = (const float4*)(g_th6 + (size_t)(r * 89) * 1536);

        unsigned long long d[4][4];
#pragma unroll
        for (int jj = 0; jj < 4; jj++)
#pragma unroll
            for (int bp = 0; bp < 4; bp++) d[jj][bp] = bc2;

#pragma unroll
        for (int pt = 0; pt < 4; pt++) {
            // spec row: 6 q, 8 batches -> sv[6][4] f32x2 (uniform LDG.128)
            unsigned long long sv[6][4];
            const float* sp = g_spec + ((p0 + pt) * NFR + qb) * BMAX + b0;
#pragma unroll
            for (int qv = 0; qv < 6; qv++) {
                ulonglong2 u0 = __ldg((const ulonglong2*)(sp + qv * BMAX));
                ulonglong2 u1 = __ldg((const ulonglong2*)(sp + qv * BMAX + 4));
                sv[qv][0] = u0.x; sv[qv][1] = u0.y;
                sv[qv][2] = u1.x; sv[qv][3] = u1.y;
            }
            // taps pt*6 .. pt*6+5 live in quads qa=(pt*6)>>2, qa+1
#pragma unroll
            for (int jj = 0; jj < 4; jj++) {
                const float4* tj = tb + (size_t)jmn[jj] * 384 + c;
                if (pt == 0) {
                    float4 A = __ldg(tj);            // taps 0-3
                    float4 Bq = __ldg(tj + 64);      // taps 4-7
                    FQ(A.x, 0); FQ(A.y, 1); FQ(A.z, 2); FQ(A.w, 3);
                    FQ(Bq.x, 4); FQ(Bq.y, 5);
                } else if (pt == 1) {
                    float4 A = __ldg(tj + 64);       // taps 4-7
                    float4 Bq = __ldg(tj + 128);     // taps 8-11
                    FQ(A.z, 0); FQ(A.w, 1);
                    FQ(Bq.x, 2); FQ(Bq.y, 3); FQ(Bq.z, 4); FQ(Bq.w, 5);
                } else if (pt == 2) {
                    float4 A = __ldg(tj + 192);      // taps 12-15
                    float4 Bq = __ldg(tj + 256);     // taps 16-19
                    FQ(A.x, 0); FQ(A.y, 1); FQ(A.z, 2); FQ(A.w, 3);
                    FQ(Bq.x, 4); FQ(Bq.y, 5);
                } else {
                    float4 A = __ldg(tj + 256);      // taps 16-19
                    float4 Bq = __ldg(tj + 320);     // taps 20-23
                    FQ(A.z, 0); FQ(A.w, 1);
                    FQ(Bq.x, 2); FQ(Bq.y, 3); FQ(Bq.z, 4); FQ(Bq.w, 5);
                }
            }
        }

        // relu + GAP accumulate
#pragma unroll
        for (int jj = 0; jj < 4; jj++) {
            if (!jv[jj]) continue;
#pragma unroll
            for (int bp = 0; bp < 4; bp++) {
                float lo, hi; UNPACK2(lo, hi, d[jj][bp]);
                acc[2 * bp]     += fmaxf(lo, 0.f);
                acc[2 * bp + 1] += fmaxf(hi, 0.f);
            }
        }
    }

    int part = rg * JT + jgt;
    float* pp = g_part + (size_t)part * (BMAX * COUT);
#pragma unroll
    for (int k = 0; k < 8; k++) {
        int b = b0 + k;
        if (b < B) pp[b * COUT + c] = acc[k];
    }
}

// ---- final: sum partials + GAP mean + FC -----------------------------------
__global__ void fc_kernel(const float* __restrict__ fw,
                          const float* __restrict__ fb,
                          float* __restrict__ out, int B) {
    __shared__ float sm[4][COUT];
    int b = blockIdx.x;
    int tid = threadIdx.x;
    int c = tid & 63, pg = tid >> 6;
    float sum = 0.f;
    for (int p = pg; p < NPARTS; p += 4)
        sum += g_part[(size_t)p * (BMAX * COUT) + b * COUT + c];
    sm[pg][c] = sum;
    __syncthreads();
    if (tid < COUT)
        sm[0][tid] += sm[1][tid] + sm[2][tid] + sm[3][tid];
    __syncthreads();
    if (tid < 5) {
        const float inv = 1.0f / (float)(CONV_OUT * CONV_OUT);
        float accv = fb[tid];
#pragma unroll 8
        for (int c2 = 0; c2 < COUT; c2++)
            accv = fmaf(sm[0][c2] * inv, fw[tid * 64 + c2], accv);
        out[b * 5 + tid] = accv;
    }
}

// ---------------------------------------------------------------------------
extern "C" void kernel_launch(void* const* d_in, const int* in_sizes, int n_in,
                              void* d_out, int out_size) {
    const float* x      = (const float*)d_in[0];
    const float* conv_w = (const float*)d_in[1];
    const float* conv_b = (const float*)d_in[2];
    const float* fc_w   = (const float*)d_in[3];
    const float* fc_b   = (const float*)d_in[4];
    float*       out    = (float*)d_out;

    int B = in_sizes[0] / SIGLEN;
    if (B > BMAX) B = BMAX;

    int prep_total = PHI_N + AY_N + TW_N;
    prep_kernel<<<(prep_total + 255) / 256, 256>>>(conv_w);

    spec_kernel<<<NPQ, 256>>>(x, B);

    dim3 tgrid(89, 23);
    theta6_kernel<<<tgrid, 256>>>();

    int chunks = (B + NB - 1) / NB;
    dim3 mgrid(JT, RG, chunks);
    tap_kernel<<<mgrid, 256>>>(conv_b, B);

    fc_kernel<<<B, 256>>>(fc_w, fc_b, out, B);
}

// round 7
// speedup vs baseline: 1.5107x; 1.1400x over previous
#include <cuda_runtime.h>
#include <math.h>

#define BMAX     256
#define SIGLEN   178
#define NFR      43
#define NFQ      33
#define NPQ      (NFQ*NFR)
#define COUT     64
#define CONV_OUT 89
#define NPARTS   184         // 92 rg * 2 jhalf

#define PHI_N    (89*4*7*64)
#define AY_N     (89*4*7)
#define TW_N     (33*7)

__device__ __align__(16) float g_spec [NPQ * BMAX];          // [p*43+q][b]
__device__ __align__(16) float g_phi  [PHI_N];               // [j][qt][ky][c]
__device__ __align__(16) float g_ay   [AY_N];                // [r][pt][ky]
__device__ __align__(16) float g_twid [33*14];
__device__ __align__(16) float g_theta[(size_t)89*89*16*64]; // [r][j][tap][c]
__device__ __align__(16) float g_part [(size_t)NPARTS * BMAX * COUT]; // [part][b][c]

// ---- shared index helpers --------------------------------------------------
__device__ __forceinline__ int q0raw(int j) {
    float sx = (2 * j - 3 + 0.5f) * (43.0f / 178.0f) - 0.5f;
    sx = fminf(fmaxf(sx, 0.f), 42.f);
    return (int)sx;
}
__device__ __forceinline__ int q0f(int j) { int q = q0raw(j); return q > 39 ? 39 : q; }
__device__ __forceinline__ int p0f(int r) {
    float sy = (2 * r - 3 + 0.5f) * (33.0f / 178.0f) - 0.5f;
    sy = fminf(fmaxf(sy, 0.f), 32.f);
    int p = (int)sy; return p > 29 ? 29 : p;
}
__device__ __forceinline__ float bweight(int x, int q) {
    if (x < 0 || x >= 178) return 0.f;
    float sx = fminf(fmaxf((x + 0.5f) * (43.0f / 178.0f) - 0.5f, 0.f), 42.f);
    int x0 = (int)sx; float fx = sx - (float)x0; int x1 = min(x0 + 1, 42);
    float w = 0.f;
    if (q == x0) w += 1.f - fx;
    if (q == x1) w += fx;
    return w;
}

#define PACK2(d, x)  asm("mov.b64 %0, {%1, %1};" : "=l"(d) : "f"(x))
#define UNPACK2(lo, hi, d) asm("mov.b64 {%0, %1}, %2;" : "=f"(lo), "=f"(hi) : "l"(d))
#define FFMA2(d, a, b) asm("fma.rn.f32x2 %0, %1, %2, %0;" : "+l"(d) : "l"(a), "l"(b))

// ---- prep ------------------------------------------------------------------
__global__ void prep_kernel(const float* __restrict__ w) {
    int t = blockIdx.x * blockDim.x + threadIdx.x;
    if (t < PHI_N) {
        int c  = t & 63;
        int u  = t >> 6;
        int ky = u % 7;  u /= 7;
        int qt = u & 3;
        int j  = u >> 2;
        int q  = q0f(j) + qt;
        const float* wc = w + c * 147 + ky * 7;
        float a = 0.f;
#pragma unroll
        for (int kx = 0; kx < 7; kx++) {
            float ws = wc[kx] + wc[49 + kx] + wc[98 + kx];
            a += ws * bweight(2 * j - 3 + kx, q);
        }
        g_phi[((j * 4 + qt) * 7 + ky) * 64 + c] = a;
    } else if (t < PHI_N + AY_N) {
        int t2 = t - PHI_N;
        int r = t2 / 28, rem = t2 % 28, pt = rem / 7, ky = rem % 7;
        int y = 2 * r - 3 + ky;
        float wgt = 0.f;
        if (y >= 0 && y < 178) {
            float sy = fminf(fmaxf((y + 0.5f) * (33.0f / 178.0f) - 0.5f, 0.f), 32.f);
            int y0 = (int)sy; float fy = sy - (float)y0; int y1 = min(y0 + 1, 32);
            int p = p0f(r) + pt;
            if (p == y0) wgt += 1.f - fy;
            if (p == y1) wgt += fy;
        }
        g_ay[t2] = wgt;
    } else if (t < PHI_N + AY_N + TW_N) {
        int t3 = t - PHI_N - AY_N;
        int k = t3 / 7, n = 1 + t3 % 7;
        float sn, cs;
        sincospif((float)(k * n) * (1.0f / 32.0f), &sn, &cs);
        g_twid[k * 14 + (n - 1) * 2]     = cs;
        g_twid[k * 14 + (n - 1) * 2 + 1] = sn;
    }
}

// ---- spectrogram -----------------------------------------------------------
__global__ void spec_kernel(const float* __restrict__ x, int B) {
    int pq = blockIdx.x;
    int b  = threadIdx.x;
    if (b >= B) return;
    int k  = pq / NFR;
    int fr = pq % NFR;

    const float* s = x + b * SIGLEN + fr * 4;
    float v[8];
    float mean = 0.f;
#pragma unroll
    for (int n = 0; n < 8; n++) { v[n] = s[n]; mean += v[n]; }
    mean *= 0.125f;

    const float* tw = g_twid + k * 14;
    float re = 0.f, im = 0.f;
#pragma unroll
    for (int n = 1; n < 8; n++) {
        float f = v[n] - mean;
        re = fmaf(f, tw[(n - 1) * 2], re);
        im = fmaf(f, -tw[(n - 1) * 2 + 1], im);
    }
    const float SCALE = sqrtf(1.0f / (178.0f * 7.0f));
    g_spec[pq * BMAX + b] = sqrtf(re * re + im * im) * SCALE;
}

// ---- theta: Theta[r][j][tap][c], tap = pt*4+qt -----------------------------
__global__ void theta_kernel() {
    int j  = blockIdx.x;
    int r0 = blockIdx.y * 4;
    int tid = threadIdx.x;
    int c = tid & 63, qt = tid >> 6;

    float f[7];
#pragma unroll
    for (int ky = 0; ky < 7; ky++)
        f[ky] = g_phi[((j * 4 + qt) * 7 + ky) * 64 + c];

#pragma unroll
    for (int rr = 0; rr < 4; rr++) {
        int r = r0 + rr;
        if (r >= CONV_OUT) break;
        const float* ay = g_ay + r * 28;
        float* dst = g_theta + (size_t)(r * 89 + j) * 1024;
#pragma unroll
        for (int pt = 0; pt < 4; pt++) {
            float th = 0.f;
#pragma unroll
            for (int ky = 0; ky < 7; ky++)
                th = fmaf(ay[pt * 7 + ky], f[ky], th);
            dst[(pt * 4 + qt) * 64 + c] = th;
        }
    }
}

// ---- main tap: outer-product 4c x 16b per thread ---------------------------
// warp: 16 c-quads x 2 b-halves; block 8 warps = 4 r-slots x 2 batch-groups
__global__ void __launch_bounds__(256, 2)
tap_kernel(const float* __restrict__ bias, int B) {
    int tid  = threadIdx.x;
    int warp = tid >> 5, lane = tid & 31;
    int qd   = lane & 15, bh = lane >> 4;
    int bgrp = warp & 1, rsub = warp >> 1;

    int jhalf = blockIdx.x;                        // 0,1
    int rg    = blockIdx.y * 4 + rsub;             // 0..91
    int b0    = blockIdx.z * 32 + bgrp * 16 + bh * 8;
    int c0    = qd * 4;

    int jlo = jhalf ? 45 : 0;
    int jhi = jhalf ? CONV_OUT : 45;

    float4 b4 = *(const float4*)(bias + c0);
    unsigned long long bb[4];
    PACK2(bb[0], b4.x); PACK2(bb[1], b4.y);
    PACK2(bb[2], b4.z); PACK2(bb[3], b4.w);

    float acc[4][8];
#pragma unroll
    for (int ci = 0; ci < 4; ci++)
#pragma unroll
        for (int k = 0; k < 8; k++) acc[ci][k] = 0.f;

    if (rg < CONV_OUT) {
        int r  = rg;
        int p0 = p0f(r);
        const float* sprow = g_spec + (p0 * NFR) * BMAX + b0;
        const float4* trow = (const float4*)(g_theta + (size_t)(r * 89) * 1024) + qd;

        for (int j = jlo; j < jhi; j++) {
            int q0 = q0f(j);
            const float4* tj = trow + (size_t)j * 256;      // tap t at tj[t*16]
            const float* sp  = sprow + q0 * BMAX;

            unsigned long long d[4][4];
#pragma unroll
            for (int ci = 0; ci < 4; ci++)
#pragma unroll
                for (int bi = 0; bi < 4; bi++) d[ci][bi] = bb[ci];

#pragma unroll
            for (int pt = 0; pt < 4; pt++) {
#pragma unroll
                for (int qt = 0; qt < 4; qt++) {
                    int t = pt * 4 + qt;
                    float4 w = __ldg(tj + t * 16);
                    const ulonglong2* s2 =
                        (const ulonglong2*)(sp + (pt * NFR + qt) * BMAX);
                    ulonglong2 u0 = __ldg(s2);
                    ulonglong2 u1 = __ldg(s2 + 1);
                    unsigned long long W0, W1, W2, W3;
                    PACK2(W0, w.x); PACK2(W1, w.y);
                    PACK2(W2, w.z); PACK2(W3, w.w);
                    FFMA2(d[0][0], W0, u0.x); FFMA2(d[0][1], W0, u0.y);
                    FFMA2(d[0][2], W0, u1.x); FFMA2(d[0][3], W0, u1.y);
                    FFMA2(d[1][0], W1, u0.x); FFMA2(d[1][1], W1, u0.y);
                    FFMA2(d[1][2], W1, u1.x); FFMA2(d[1][3], W1, u1.y);
                    FFMA2(d[2][0], W2, u0.x); FFMA2(d[2][1], W2, u0.y);
                    FFMA2(d[2][2], W2, u1.x); FFMA2(d[2][3], W2, u1.y);
                    FFMA2(d[3][0], W3, u0.x); FFMA2(d[3][1], W3, u0.y);
                    FFMA2(d[3][2], W3, u1.x); FFMA2(d[3][3], W3, u1.y);
                }
            }
            // relu + GAP accumulate
#pragma unroll
            for (int ci = 0; ci < 4; ci++)
#pragma unroll
                for (int bi = 0; bi < 4; bi++) {
                    float lo, hi; UNPACK2(lo, hi, d[ci][bi]);
                    acc[ci][2 * bi]     += fmaxf(lo, 0.f);
                    acc[ci][2 * bi + 1] += fmaxf(hi, 0.f);
                }
        }
    }

    // store partials [part][b][c]
    int part = rg * 2 + jhalf;
    float* pp = g_part + ((size_t)part * BMAX) * COUT + c0;
#pragma unroll
    for (int k = 0; k < 8; k++) {
        int b = b0 + k;
        if (b < B) {
            float4 v = make_float4(acc[0][k], acc[1][k], acc[2][k], acc[3][k]);
            *(float4*)(pp + (size_t)b * COUT) = v;
        }
    }
}

// ---- final: sum partials + GAP mean + FC -----------------------------------
__global__ void fc_kernel(const float* __restrict__ fw,
                          const float* __restrict__ fb,
                          float* __restrict__ out, int B) {
    __shared__ float sm[4][COUT];
    int b = blockIdx.x;
    int tid = threadIdx.x;
    int c = tid & 63, pg = tid >> 6;
    float sum = 0.f;
    for (int p = pg; p < NPARTS; p += 4)
        sum += g_part[((size_t)p * BMAX + b) * COUT + c];
    sm[pg][c] = sum;
    __syncthreads();
    if (tid < COUT)
        sm[0][tid] += sm[1][tid] + sm[2][tid] + sm[3][tid];
    __syncthreads();
    if (tid < 5) {
        const float inv = 1.0f / (float)(CONV_OUT * CONV_OUT);
        float accv = fb[tid];
#pragma unroll 8
        for (int c2 = 0; c2 < COUT; c2++)
            accv = fmaf(sm[0][c2] * inv, fw[tid * 64 + c2], accv);
        out[b * 5 + tid] = accv;
    }
}

// ---------------------------------------------------------------------------
extern "C" void kernel_launch(void* const* d_in, const int* in_sizes, int n_in,
                              void* d_out, int out_size) {
    const float* x      = (const float*)d_in[0];
    const float* conv_w = (const float*)d_in[1];
    const float* conv_b = (const float*)d_in[2];
    const float* fc_w   = (const float*)d_in[3];
    const float* fc_b   = (const float*)d_in[4];
    float*       out    = (float*)d_out;

    int B = in_sizes[0] / SIGLEN;
    if (B > BMAX) B = BMAX;

    int prep_total = PHI_N + AY_N + TW_N;
    prep_kernel<<<(prep_total + 255) / 256, 256>>>(conv_w);

    spec_kernel<<<NPQ, 256>>>(x, B);

    dim3 tgrid(89, 23);
    theta_kernel<<<tgrid, 256>>>();

    int chunks = (B + 31) / 32;
    dim3 mgrid(2, 23, chunks);
    tap_kernel<<<mgrid, 256>>>(conv_b, B);

    fc_kernel<<<B, 256>>>(fc_w, fc_b, out, B);
}

// round 8
// speedup vs baseline: 1.7770x; 1.1762x over previous
#include <cuda_runtime.h>
#include <math.h>

#define BMAX     256
#define SIGLEN   178
#define NFR      43
#define NFQ      33
#define NPQ      (NFQ*NFR)
#define COUT     64
#define CONV_OUT 89
#define NSTEP    12          // ceil(89/8) j-steps

#define PHI_N    (89*4*7*64)
#define AY_N     (89*4*7)
#define TW_N     (33*7)

__device__ __align__(16) float g_spec [NPQ * BMAX];          // [p*43+q][b]
__device__ __align__(16) float g_phi  [PHI_N];               // [j][qt][ky][c]
__device__ __align__(16) float g_ay   [AY_N];                // [r][pt][ky]
__device__ __align__(16) float g_twid [33*14];
__device__ __align__(16) float g_theta[(size_t)89*89*16*64]; // [r][j][tap][c]
__device__ __align__(16) float g_part [(size_t)CONV_OUT * BMAX * COUT]; // [r][b][c]

// ---- shared index helpers --------------------------------------------------
__device__ __forceinline__ int q0raw(int j) {
    float sx = (2 * j - 3 + 0.5f) * (43.0f / 178.0f) - 0.5f;
    sx = fminf(fmaxf(sx, 0.f), 42.f);
    return (int)sx;
}
__device__ __forceinline__ int q0f(int j) { int q = q0raw(j); return q > 39 ? 39 : q; }
__device__ __forceinline__ int p0f(int r) {
    float sy = (2 * r - 3 + 0.5f) * (33.0f / 178.0f) - 0.5f;
    sy = fminf(fmaxf(sy, 0.f), 32.f);
    int p = (int)sy; return p > 29 ? 29 : p;
}
__device__ __forceinline__ float bweight(int x, int q) {
    if (x < 0 || x >= 178) return 0.f;
    float sx = fminf(fmaxf((x + 0.5f) * (43.0f / 178.0f) - 0.5f, 0.f), 42.f);
    int x0 = (int)sx; float fx = sx - (float)x0; int x1 = min(x0 + 1, 42);
    float w = 0.f;
    if (q == x0) w += 1.f - fx;
    if (q == x1) w += fx;
    return w;
}

#define PACK2(d, x)  asm("mov.b64 %0, {%1, %1};" : "=l"(d) : "f"(x))
#define UNPACK2(lo, hi, d) asm("mov.b64 {%0, %1}, %2;" : "=f"(lo), "=f"(hi) : "l"(d))
#define FFMA2(d, a, b) asm("fma.rn.f32x2 %0, %1, %2, %0;" : "+l"(d) : "l"(a), "l"(b))
#define LDS128F(v, ad) asm volatile("ld.shared.v4.f32 {%0,%1,%2,%3}, [%4];" \
    : "=f"(v.x), "=f"(v.y), "=f"(v.z), "=f"(v.w) : "r"(ad))
#define CPASYNC16(dst, src) asm volatile( \
    "cp.async.cg.shared.global [%0], [%1], 16;" :: "r"(dst), "l"(src))
#define CPCOMMIT() asm volatile("cp.async.commit_group;")
#define CPWAIT1()  asm volatile("cp.async.wait_group 1;")
#define CPWAIT0()  asm volatile("cp.async.wait_group 0;")

// ---- prep ------------------------------------------------------------------
__global__ void prep_kernel(const float* __restrict__ w) {
    int t = blockIdx.x * blockDim.x + threadIdx.x;
    if (t < PHI_N) {
        int c  = t & 63;
        int u  = t >> 6;
        int ky = u % 7;  u /= 7;
        int qt = u & 3;
        int j  = u >> 2;
        int q  = q0f(j) + qt;
        const float* wc = w + c * 147 + ky * 7;
        float a = 0.f;
#pragma unroll
        for (int kx = 0; kx < 7; kx++) {
            float ws = wc[kx] + wc[49 + kx] + wc[98 + kx];
            a += ws * bweight(2 * j - 3 + kx, q);
        }
        g_phi[((j * 4 + qt) * 7 + ky) * 64 + c] = a;
    } else if (t < PHI_N + AY_N) {
        int t2 = t - PHI_N;
        int r = t2 / 28, rem = t2 % 28, pt = rem / 7, ky = rem % 7;
        int y = 2 * r - 3 + ky;
        float wgt = 0.f;
        if (y >= 0 && y < 178) {
            float sy = fminf(fmaxf((y + 0.5f) * (33.0f / 178.0f) - 0.5f, 0.f), 32.f);
            int y0 = (int)sy; float fy = sy - (float)y0; int y1 = min(y0 + 1, 32);
            int p = p0f(r) + pt;
            if (p == y0) wgt += 1.f - fy;
            if (p == y1) wgt += fy;
        }
        g_ay[t2] = wgt;
    } else if (t < PHI_N + AY_N + TW_N) {
        int t3 = t - PHI_N - AY_N;
        int k = t3 / 7, n = 1 + t3 % 7;
        float sn, cs;
        sincospif((float)(k * n) * (1.0f / 32.0f), &sn, &cs);
        g_twid[k * 14 + (n - 1) * 2]     = cs;
        g_twid[k * 14 + (n - 1) * 2 + 1] = sn;
    }
}

// ---- spectrogram -----------------------------------------------------------
__global__ void spec_kernel(const float* __restrict__ x, int B) {
    int pq = blockIdx.x;
    int b  = threadIdx.x;
    if (b >= B) return;
    int k  = pq / NFR;
    int fr = pq % NFR;

    const float* s = x + b * SIGLEN + fr * 4;
    float v[8];
    float mean = 0.f;
#pragma unroll
    for (int n = 0; n < 8; n++) { v[n] = s[n]; mean += v[n]; }
    mean *= 0.125f;

    const float* tw = g_twid + k * 14;
    float re = 0.f, im = 0.f;
#pragma unroll
    for (int n = 1; n < 8; n++) {
        float f = v[n] - mean;
        re = fmaf(f, tw[(n - 1) * 2], re);
        im = fmaf(f, -tw[(n - 1) * 2 + 1], im);
    }
    const float SCALE = sqrtf(1.0f / (178.0f * 7.0f));
    g_spec[pq * BMAX + b] = sqrtf(re * re + im * im) * SCALE;
}

// ---- theta: Theta[r][j][tap][c], tap = pt*4+qt -----------------------------
__global__ void theta_kernel() {
    int j  = blockIdx.x;
    int r0 = blockIdx.y * 4;
    int tid = threadIdx.x;
    int c = tid & 63, qt = tid >> 6;

    float f[7];
#pragma unroll
    for (int ky = 0; ky < 7; ky++)
        f[ky] = g_phi[((j * 4 + qt) * 7 + ky) * 64 + c];

#pragma unroll
    for (int rr = 0; rr < 4; rr++) {
        int r = r0 + rr;
        if (r >= CONV_OUT) break;
        const float* ay = g_ay + r * 28;
        float* dst = g_theta + (size_t)(r * 89 + j) * 1024;
#pragma unroll
        for (int pt = 0; pt < 4; pt++) {
            float th = 0.f;
#pragma unroll
            for (int ky = 0; ky < 7; ky++)
                th = fmaf(ay[pt * 7 + ky], f[ky], th);
            dst[(pt * 4 + qt) * 64 + c] = th;
        }
    }
}

// ---- main tap: cp.async Θ pipeline, 8 j-streams, 4c x 8b threads -----------
// block = (r, 16 batches); warp w handles j = step*8 + w
__global__ void __launch_bounds__(256, 2)
tap_kernel(const float* __restrict__ bias, int B) {
    extern __shared__ float smem_raw[];   // 64 KB: 2 buffers x 8 slabs x 1024 f
    int tid  = threadIdx.x;
    int lane = tid & 31, w = tid >> 5;
    int qd   = lane & 15, bh = lane >> 4;

    int item   = blockIdx.x;              // r * 16 + bchunk
    int r      = item >> 4;
    int bchunk = item & 15;
    int b0     = bchunk * 16 + bh * 8;
    int c0     = qd * 4;

    unsigned sb;
    asm("{ .reg .u64 t; cvta.to.shared.u64 t, %1; cvt.u32.u64 %0, t; }"
        : "=r"(sb) : "l"(smem_raw));

    int p0 = p0f(r);
    const float* sprow = g_spec + (p0 * NFR) * BMAX + b0;

    float4 b4 = *(const float4*)(bias + c0);
    unsigned long long bb[4];
    PACK2(bb[0], b4.x); PACK2(bb[1], b4.y);
    PACK2(bb[2], b4.z); PACK2(bb[3], b4.w);

    float acc[4][8];
#pragma unroll
    for (int ci = 0; ci < 4; ci++)
#pragma unroll
        for (int k = 0; k < 8; k++) acc[ci][k] = 0.f;

    const float* tsrc_base = g_theta + (size_t)r * (89 * 1024) + tid * 4;

    // ---- stage step s into buffer buf
#define STAGE(s, buf) do {                                                  \
        int _s = (s);                                                       \
        unsigned _d = sb + (unsigned)((buf) * 32768 + tid * 16);            \
        _Pragma("unroll")                                                   \
        for (int k = 0; k < 8; k++) {                                       \
            int jk = _s * 8 + k;                                            \
            if (jk < CONV_OUT)                                              \
                CPASYNC16(_d + (unsigned)(k * 4096),                        \
                          tsrc_base + (size_t)jk * 1024);                   \
        }                                                                   \
    } while (0)

    STAGE(0, 0); CPCOMMIT();

    for (int s = 0; s < NSTEP; s++) {
        if (s + 1 < NSTEP) { STAGE(s + 1, (s + 1) & 1); CPCOMMIT(); CPWAIT1(); }
        else               { CPWAIT0(); }
        __syncthreads();

        int j = s * 8 + w;
        if (j < CONV_OUT) {
            int q0 = q0f(j);
            const float* sp = sprow + q0 * BMAX;
            unsigned slab = sb + (unsigned)(((s & 1) * 32768) + w * 4096 + qd * 16);

            unsigned long long d[4][4];
#pragma unroll
            for (int ci = 0; ci < 4; ci++)
#pragma unroll
                for (int bi = 0; bi < 4; bi++) d[ci][bi] = bb[ci];

#pragma unroll
            for (int pt = 0; pt < 4; pt++) {
#pragma unroll
                for (int qt = 0; qt < 4; qt++) {
                    int t = pt * 4 + qt;
                    float4 wv;
                    LDS128F(wv, slab + (unsigned)(t * 256));
                    const ulonglong2* s2 =
                        (const ulonglong2*)(sp + (pt * NFR + qt) * BMAX);
                    ulonglong2 u0 = __ldg(s2);
                    ulonglong2 u1 = __ldg(s2 + 1);
                    unsigned long long W0, W1, W2, W3;
                    PACK2(W0, wv.x); PACK2(W1, wv.y);
                    PACK2(W2, wv.z); PACK2(W3, wv.w);
                    FFMA2(d[0][0], W0, u0.x); FFMA2(d[0][1], W0, u0.y);
                    FFMA2(d[0][2], W0, u1.x); FFMA2(d[0][3], W0, u1.y);
                    FFMA2(d[1][0], W1, u0.x); FFMA2(d[1][1], W1, u0.y);
                    FFMA2(d[1][2], W1, u1.x); FFMA2(d[1][3], W1, u1.y);
                    FFMA2(d[2][0], W2, u0.x); FFMA2(d[2][1], W2, u0.y);
                    FFMA2(d[2][2], W2, u1.x); FFMA2(d[2][3], W2, u1.y);
                    FFMA2(d[3][0], W3, u0.x); FFMA2(d[3][1], W3, u0.y);
                    FFMA2(d[3][2], W3, u1.x); FFMA2(d[3][3], W3, u1.y);
                }
            }
#pragma unroll
            for (int ci = 0; ci < 4; ci++)
#pragma unroll
                for (int bi = 0; bi < 4; bi++) {
                    float lo, hi; UNPACK2(lo, hi, d[ci][bi]);
                    acc[ci][2 * bi]     += fmaxf(lo, 0.f);
                    acc[ci][2 * bi + 1] += fmaxf(hi, 0.f);
                }
        }
        __syncthreads();
    }

    // ---- cross-warp reduce (8 j-streams -> one partial per (b,c)) ----------
    float4* rs = (float4*)smem_raw;       // [w][16 b][16 c-quads]
#pragma unroll
    for (int bi = 0; bi < 8; bi++)
        rs[w * 256 + (bh * 8 + bi) * 16 + qd] =
            make_float4(acc[0][bi], acc[1][bi], acc[2][bi], acc[3][bi]);
    __syncthreads();

    int ob  = tid >> 4;                   // 0..15 batch within chunk
    int oc4 = tid & 15;                   // c-quad
    float4 v = rs[ob * 16 + oc4];
#pragma unroll
    for (int ww = 1; ww < 8; ww++) {
        float4 u = rs[ww * 256 + ob * 16 + oc4];
        v.x += u.x; v.y += u.y; v.z += u.z; v.w += u.w;
    }
    int b = bchunk * 16 + ob;
    if (b < B)
        *(float4*)(g_part + ((size_t)r * BMAX + b) * COUT + oc4 * 4) = v;
}

// ---- final: sum partials over r + GAP mean + FC ----------------------------
__global__ void fc_kernel(const float* __restrict__ fw,
                          const float* __restrict__ fb,
                          float* __restrict__ out, int B) {
    __shared__ float sm[4][COUT];
    int b = blockIdx.x;
    int tid = threadIdx.x;
    int c = tid & 63, pg = tid >> 6;
    float sum = 0.f;
    for (int rr = pg; rr < CONV_OUT; rr += 4)
        sum += g_part[((size_t)rr * BMAX + b) * COUT + c];
    sm[pg][c] = sum;
    __syncthreads();
    if (tid < COUT)
        sm[0][tid] += sm[1][tid] + sm[2][tid] + sm[3][tid];
    __syncthreads();
    if (tid < 5) {
        const float inv = 1.0f / (float)(CONV_OUT * CONV_OUT);
        float accv = fb[tid];
#pragma unroll 8
        for (int c2 = 0; c2 < COUT; c2++)
            accv = fmaf(sm[0][c2] * inv, fw[tid * 64 + c2], accv);
        out[b * 5 + tid] = accv;
    }
}

// ---------------------------------------------------------------------------
extern "C" void kernel_launch(void* const* d_in, const int* in_sizes, int n_in,
                              void* d_out, int out_size) {
    const float* x      = (const float*)d_in[0];
    const float* conv_w = (const float*)d_in[1];
    const float* conv_b = (const float*)d_in[2];
    const float* fc_w   = (const float*)d_in[3];
    const float* fc_b   = (const float*)d_in[4];
    float*       out    = (float*)d_out;

    int B = in_sizes[0] / SIGLEN;
    if (B > BMAX) B = BMAX;

    cudaFuncSetAttribute(tap_kernel,
                         cudaFuncAttributeMaxDynamicSharedMemorySize, 65536);

    int prep_total = PHI_N + AY_N + TW_N;
    prep_kernel<<<(prep_total + 255) / 256, 256>>>(conv_w);

    spec_kernel<<<NPQ, 256>>>(x, B);

    dim3 tgrid(89, 23);
    theta_kernel<<<tgrid, 256>>>();

    tap_kernel<<<CONV_OUT * 16, 256, 65536>>>(conv_b, B);

    fc_kernel<<<B, 256>>>(fc_w, fc_b, out, B);
}